// round 5
// baseline (speedup 1.0000x reference)
#include <cuda_runtime.h>

// Scratch (no allocations allowed): s = scaled B-projection, k = conv taps.
__device__ __align__(16) float g_s[4 * 16 * 64];      // [b][u][n]
__device__ __align__(16) float g_k[4 * 16 * 1024];    // [b][u][m]

#define TAPS 16
#define BQ 4
#define LQ 2048
#define DMQ 1024
#define NQ 64

// ---------------------------------------------------------------------------
// K1: s[b,u,n] = (dot(x[b,u,:], W_B[n,:]) + b_B[n]) * exp(u * log_A[n])
// grid = 1024: (64 (b,u)) x (16 n-groups of 4). Block = 128 = 4 warps,
// one warp per n. All 8 W_B float4 loads front-batched into registers (MLP=8).
// ---------------------------------------------------------------------------
__global__ void __launch_bounds__(128) s4_k1(const float* __restrict__ x,
                                             const float* __restrict__ W_B,
                                             const float* __restrict__ b_B,
                                             const float* __restrict__ log_A) {
    int bu = blockIdx.x >> 4;            // 0..63
    int ng = blockIdx.x & 15;            // n-group of 4
    int b = bu >> 4;
    int u = bu & 15;

    __shared__ float4 xs[DMQ / 4];
    const float4* xr = reinterpret_cast<const float4*>(x + ((size_t)b * LQ + u) * DMQ);
    xs[threadIdx.x]       = xr[threadIdx.x];
    xs[threadIdx.x + 128] = xr[threadIdx.x + 128];
    __syncthreads();

    int w = threadIdx.x >> 5;
    int lane = threadIdx.x & 31;
    int n = ng * 4 + w;

    const float4* wr = reinterpret_cast<const float4*>(W_B + (size_t)n * DMQ);
    float4 wv[8];
    #pragma unroll
    for (int j = 0; j < 8; j++) wv[j] = wr[lane + 32 * j];   // 8 independent LDG.128

    float p0 = 0.0f, p1 = 0.0f;
    #pragma unroll
    for (int j = 0; j < 8; j++) {
        float4 a = xs[lane + 32 * j];
        p0 += a.x * wv[j].x + a.y * wv[j].y;
        p1 += a.z * wv[j].z + a.w * wv[j].w;
    }
    float p = p0 + p1;
    #pragma unroll
    for (int off = 16; off; off >>= 1) p += __shfl_xor_sync(0xFFFFFFFFu, p, off);

    if (lane == 0) {
        float e = expf((float)u * log_A[n]);   // underflows to 0 like the reference
        g_s[bu * NQ + n] = (p + b_B[n]) * e;
    }
}

// ---------------------------------------------------------------------------
// K2: k[b,u,m] = sum_n s[b,u,n] * C[n,m]
// grid = (16 m-tiles of 64, 16 (b, u-group of 4)), block = (64, 4): ty = u in
// group. The 4 ty threads at one m hit the same C[n,m] -> L1 broadcast.
// ---------------------------------------------------------------------------
__global__ void __launch_bounds__(256) s4_k2(const float* __restrict__ C) {
    int b  = blockIdx.y >> 2;
    int ug = blockIdx.y & 3;
    int bu = b * TAPS + ug * 4 + threadIdx.y;
    int m  = blockIdx.x * 64 + threadIdx.x;

    __shared__ float s[4][NQ];
    int tid = threadIdx.y * 64 + threadIdx.x;
    if (tid < 4 * NQ)
        s[tid >> 6][tid & 63] = g_s[(b * TAPS + ug * 4) * NQ + tid];
    __syncthreads();

    float acc = 0.0f;
    const float* sr = s[threadIdx.y];
    #pragma unroll
    for (int n = 0; n < NQ; n++) acc += sr[n] * C[(size_t)n * DMQ + m];

    g_k[(size_t)bu * DMQ + m] = acc;
}

// ---------------------------------------------------------------------------
// K3: 16-tap per-channel causal FIR + D skip, packed f32x2 math.
// Thread = one channel pair (2 adjacent m) x 16 consecutive t outputs.
// Taps streamed from global inside the loop (L1-resident) to cut regs.
// grid = (2 c-tiles, 128 t-tiles, 4 b), block = 256.
// ---------------------------------------------------------------------------
typedef unsigned long long u64t;

__device__ __forceinline__ u64t ffma2(u64t a, u64t b, u64t c) {
    u64t d;
    asm("fma.rn.f32x2 %0, %1, %2, %3;" : "=l"(d) : "l"(a), "l"(b), "l"(c));
    return d;
}
__device__ __forceinline__ u64t fmul2(u64t a, u64t b) {
    u64t d;
    asm("mul.rn.f32x2 %0, %1, %2;" : "=l"(d) : "l"(a), "l"(b));
    return d;
}

__global__ void __launch_bounds__(256) s4_k3(const float* __restrict__ x,
                                             const float* __restrict__ D,
                                             float* __restrict__ out) {
    const int S = DMQ / 2;                       // row stride in pairs
    int c  = blockIdx.x * 256 + threadIdx.x;     // 0..511 channel pair
    int t0 = blockIdx.y * 16;
    int b  = blockIdx.z;

    const u64t* xp = reinterpret_cast<const u64t*>(x) + (size_t)b * LQ * S + c;
    const u64t* kp = reinterpret_cast<const u64t*>(g_k) + (size_t)b * TAPS * S + c;

    u64t dp = reinterpret_cast<const u64t*>(D)[c];

    // x window: t = t0-15 .. t0+15  (31 pairs), zero below t=0
    u64t win[31];
    #pragma unroll
    for (int i = 0; i < 31; i++) {
        int t = t0 - 15 + i;
        win[i] = (t >= 0) ? xp[(size_t)t * S] : 0ull;   // 0x0 == {+0.f,+0.f}
    }

    u64t acc[16];
    #pragma unroll
    for (int j = 0; j < 16; j++) acc[j] = fmul2(win[15 + j], dp);   // D skip

    #pragma unroll
    for (int u = 0; u < TAPS; u++) {
        u64t kt = kp[(size_t)u * S];             // streamed, L1/L2-resident
        #pragma unroll
        for (int j = 0; j < 16; j++)
            acc[j] = ffma2(kt, win[15 + j - u], acc[j]);
    }

    u64t* op = reinterpret_cast<u64t*>(out) + (size_t)b * LQ * S + c;
    #pragma unroll
    for (int j = 0; j < 16; j++) op[(size_t)(t0 + j) * S] = acc[j];
}

// ---------------------------------------------------------------------------
extern "C" void kernel_launch(void* const* d_in, const int* in_sizes, int n_in,
                              void* d_out, int out_size) {
    const float* x     = (const float*)d_in[0];   // (4, 2048, 1024)
    const float* W_B   = (const float*)d_in[1];   // (64, 1024)
    const float* b_B   = (const float*)d_in[2];   // (64,)
    const float* C     = (const float*)d_in[3];   // (64, 1024)
    const float* D     = (const float*)d_in[4];   // (1024,)
    const float* log_A = (const float*)d_in[5];   // (64,)
    float* out = (float*)d_out;

    s4_k1<<<1024, 128>>>(x, W_B, b_B, log_A);
    s4_k2<<<dim3(16, 16), dim3(64, 4)>>>(C);
    s4_k3<<<dim3(2, 128, 4), 256>>>(x, D, out);
}

// round 6
// speedup vs baseline: 1.5473x; 1.5473x over previous
#include <cuda_runtime.h>

// Scratch (no allocations allowed): s = scaled B-projection, k = conv taps.
__device__ __align__(16) float g_s[4 * 16 * 64];      // [b][u][n]
__device__ __align__(16) float g_k[4 * 16 * 1024];    // [b][u][m]

#define TAPS 16
#define BQ 4
#define LQ 2048
#define DMQ 1024
#define NQ 64

// ---------------------------------------------------------------------------
// K1: s[b,u,n] = (dot(x[b,u,:], W_B[n,:]) + b_B[n]) * exp(u * log_A[n])
// grid = 1024: (64 (b,u)) x (16 n-groups of 4). Block = 128 = 4 warps,
// one warp per n. NO smem, NO barrier: 16 front-batched LDG.128 per lane
// (8 x + 8 W_B); x row is L2-shared by the 64 warps that read it.
// ---------------------------------------------------------------------------
__global__ void __launch_bounds__(128) s4_k1(const float* __restrict__ x,
                                             const float* __restrict__ W_B,
                                             const float* __restrict__ b_B,
                                             const float* __restrict__ log_A) {
    int bu = blockIdx.x >> 4;            // 0..63
    int ng = blockIdx.x & 15;            // n-group of 4
    int b = bu >> 4;
    int u = bu & 15;

    int w = threadIdx.x >> 5;
    int lane = threadIdx.x & 31;
    int n = ng * 4 + w;

    const float4* xr = reinterpret_cast<const float4*>(x + ((size_t)b * LQ + u) * DMQ);
    const float4* wr = reinterpret_cast<const float4*>(W_B + (size_t)n * DMQ);

    float4 xv[8], wv[8];
    #pragma unroll
    for (int j = 0; j < 8; j++) xv[j] = xr[lane + 32 * j];   // 16 independent
    #pragma unroll
    for (int j = 0; j < 8; j++) wv[j] = wr[lane + 32 * j];   // LDG.128 total

    float p0 = 0.0f, p1 = 0.0f;
    #pragma unroll
    for (int j = 0; j < 8; j++) {
        p0 += xv[j].x * wv[j].x + xv[j].y * wv[j].y;
        p1 += xv[j].z * wv[j].z + xv[j].w * wv[j].w;
    }
    float p = p0 + p1;
    #pragma unroll
    for (int off = 16; off; off >>= 1) p += __shfl_xor_sync(0xFFFFFFFFu, p, off);

    if (lane == 0) {
        float e = expf((float)u * log_A[n]);   // underflows to 0 like the reference
        g_s[bu * NQ + n] = (p + b_B[n]) * e;
    }
}

// ---------------------------------------------------------------------------
// K2: k[b,u,m] = sum_n s[b,u,n] * C[n,m]
// grid = (16 m-tiles of 64, 16 (b, u-group of 4)), block = (64, 4): ty = u in
// group. The 4 ty threads at one m hit the same C[n,m] -> L1 broadcast.
// ---------------------------------------------------------------------------
__global__ void __launch_bounds__(256) s4_k2(const float* __restrict__ C) {
    int b  = blockIdx.y >> 2;
    int ug = blockIdx.y & 3;
    int bu = b * TAPS + ug * 4 + threadIdx.y;
    int m  = blockIdx.x * 64 + threadIdx.x;

    __shared__ float s[4][NQ];
    int tid = threadIdx.y * 64 + threadIdx.x;
    if (tid < 4 * NQ)
        s[tid >> 6][tid & 63] = g_s[(b * TAPS + ug * 4) * NQ + tid];
    __syncthreads();

    float acc = 0.0f;
    const float* sr = s[threadIdx.y];
    #pragma unroll
    for (int n = 0; n < NQ; n++) acc += sr[n] * C[(size_t)n * DMQ + m];

    g_k[(size_t)bu * DMQ + m] = acc;
}

// ---------------------------------------------------------------------------
// K3: 16-tap per-channel causal FIR + D skip, packed f32x2 math.
// Thread = one channel pair (2 adjacent m) x 16 consecutive t outputs.
// Taps CACHED in registers (streamed version measured ~2.4x slower).
// grid = (2 c-tiles, 128 t-tiles, 4 b), block = 256.
// ---------------------------------------------------------------------------
typedef unsigned long long u64t;

__device__ __forceinline__ u64t ffma2(u64t a, u64t b, u64t c) {
    u64t d;
    asm("fma.rn.f32x2 %0, %1, %2, %3;" : "=l"(d) : "l"(a), "l"(b), "l"(c));
    return d;
}
__device__ __forceinline__ u64t fmul2(u64t a, u64t b) {
    u64t d;
    asm("mul.rn.f32x2 %0, %1, %2;" : "=l"(d) : "l"(a), "l"(b));
    return d;
}

__global__ void __launch_bounds__(256) s4_k3(const float* __restrict__ x,
                                             const float* __restrict__ D,
                                             float* __restrict__ out) {
    const int S = DMQ / 2;                       // row stride in pairs
    int c  = blockIdx.x * 256 + threadIdx.x;     // 0..511 channel pair
    int t0 = blockIdx.y * 16;
    int b  = blockIdx.z;

    const u64t* xp = reinterpret_cast<const u64t*>(x) + (size_t)b * LQ * S + c;
    const u64t* kp = reinterpret_cast<const u64t*>(g_k) + (size_t)b * TAPS * S + c;

    u64t kr[TAPS];
    #pragma unroll
    for (int u = 0; u < TAPS; u++) kr[u] = kp[(size_t)u * S];

    u64t dp = reinterpret_cast<const u64t*>(D)[c];

    // x window: t = t0-15 .. t0+15  (31 pairs), zero below t=0
    u64t win[31];
    #pragma unroll
    for (int i = 0; i < 31; i++) {
        int t = t0 - 15 + i;
        win[i] = (t >= 0) ? xp[(size_t)t * S] : 0ull;   // 0x0 == {+0.f,+0.f}
    }

    u64t acc[16];
    #pragma unroll
    for (int j = 0; j < 16; j++) acc[j] = fmul2(win[15 + j], dp);   // D skip

    #pragma unroll
    for (int u = 0; u < TAPS; u++) {
        #pragma unroll
        for (int j = 0; j < 16; j++)
            acc[j] = ffma2(kr[u], win[15 + j - u], acc[j]);
    }

    u64t* op = reinterpret_cast<u64t*>(out) + (size_t)b * LQ * S + c;
    #pragma unroll
    for (int j = 0; j < 16; j++) op[(size_t)(t0 + j) * S] = acc[j];
}

// ---------------------------------------------------------------------------
extern "C" void kernel_launch(void* const* d_in, const int* in_sizes, int n_in,
                              void* d_out, int out_size) {
    const float* x     = (const float*)d_in[0];   // (4, 2048, 1024)
    const float* W_B   = (const float*)d_in[1];   // (64, 1024)
    const float* b_B   = (const float*)d_in[2];   // (64,)
    const float* C     = (const float*)d_in[3];   // (64, 1024)
    const float* D     = (const float*)d_in[4];   // (1024,)
    const float* log_A = (const float*)d_in[5];   // (64,)
    float* out = (float*)d_out;

    s4_k1<<<1024, 128>>>(x, W_B, b_B, log_A);
    s4_k2<<<dim3(16, 16), dim3(64, 4)>>>(C);
    s4_k3<<<dim3(2, 128, 4), 256>>>(x, D, out);
}